// round 13
// baseline (speedup 1.0000x reference)
#include <cuda_runtime.h>
#include <cuda_bf16.h>
#include <math.h>
#include <cstdint>

#define B_ 8
#define S_ 256
#define V_ 32000
#define E_ 512
#define H_ 1024
#define G_ 3072      // 3H
#define T_ 2048      // B*S
#define F_ 1536      // H+E
#define NT_ 250      // V/128 score tiles per row
#define NT2_ 500     // per-row softmax partials
#define GRU_CTAS 128
#define LDKW 516     // u32 words per batch row in h_s (1032 bf16, bank-spread)

// ---------------- scratch (static device globals; no allocation) ----------------
__device__ uint4 g_wfrag[(size_t)GRU_CTAS * 4096];       // W_hh bf16 MMA A-fragments, 64KB/CTA
__device__ __nv_bfloat16 g_featbf[(size_t)T_ * F_];      // bf16 feat: ctx | emb
__device__ float g_gx[(size_t)T_ * G_];                  // input gates (fp32)
__device__ __nv_bfloat16 g_embh[(size_t)V_ * E_];        // emb table bf16
__device__ __nv_bfloat16 g_linbf[(size_t)E_ * F_];       // lin_W bf16
__device__ __nv_bfloat16 g_wihbf[(size_t)G_ * E_];       // W_ih bf16
__device__ __nv_bfloat16 g_logbf[(size_t)T_ * E_];       // logits bf16
__device__ float2 g_part[(size_t)T_ * NT2_];             // (max, sumexp) partials
__device__ float g_lse[T_];
__device__ __nv_bfloat16 g_hbuf16[2 * B_ * H_];          // ping-pong h exchange, bf16 [b][k]
__device__ unsigned int g_arr[GRU_CTAS * 32];            // per-CTA arrival slots (128B spread)

// ---------------- helpers ----------------
__device__ __forceinline__ uint32_t smem_u32(const void* p) {
    uint32_t a;
    asm("{ .reg .u64 t; cvta.to.shared.u64 t, %1; cvt.u32.u64 %0, t; }" : "=r"(a) : "l"(p));
    return a;
}
__device__ __forceinline__ void ldsm4(uint32_t& r0, uint32_t& r1, uint32_t& r2, uint32_t& r3,
                                      uint32_t addr) {
    asm volatile("ldmatrix.sync.aligned.m8n8.x4.shared.b16 {%0,%1,%2,%3}, [%4];"
                 : "=r"(r0), "=r"(r1), "=r"(r2), "=r"(r3) : "r"(addr));
}
__device__ __forceinline__ void mma16816(float* c, const uint32_t* a, uint32_t b0, uint32_t b1) {
    asm volatile(
        "mma.sync.aligned.m16n8k16.row.col.f32.bf16.bf16.f32 "
        "{%0,%1,%2,%3}, {%4,%5,%6,%7}, {%8,%9}, {%0,%1,%2,%3};"
        : "+f"(c[0]), "+f"(c[1]), "+f"(c[2]), "+f"(c[3])
        : "r"(a[0]), "r"(a[1]), "r"(a[2]), "r"(a[3]), "r"(b0), "r"(b1));
}

// ---------------- K1: fused prep ----------------
#define PREP_EMBED0   GRU_CTAS                              // 128
#define PREP_CVTE0    (PREP_EMBED0 + T_)                    // 2176
#define PREP_CVTL0    (PREP_CVTE0 + (V_ * E_ / 4) / 256)    // 18176
#define PREP_CVTW0    (PREP_CVTL0 + (E_ * F_ / 4) / 256)    // 18944
#define PREP_BLOCKS   (PREP_CVTW0 + (G_ * E_ / 4) / 256)    // 20480

__global__ void __launch_bounds__(256) prep_kernel(
    const float* __restrict__ W_hh, const int* __restrict__ x,
    const float* __restrict__ emb_W, const float* __restrict__ lin_W,
    const float* __restrict__ W_ih)
{
    const int bid = blockIdx.x, tid = threadIdx.x;
    if (bid < PREP_EMBED0) {
        // ---- pack W_hh into mma.m16n8k16 A-fragments (bf16) for CTA c ----
        int c = bid;
        if (c == 0) {
            for (int i = tid; i < GRU_CTAS * 32; i += 256) g_arr[i] = 0u;
        }
        for (int it = 0; it < 16; ++it) {
            int li = it * 256 + tid;              // uint4 index within this CTA's block
            int w = li >> 9, rest = li & 511;
            int t = rest >> 6, rest2 = rest & 63;
            int m = rest2 >> 5, lane = rest2 & 31;
            uint32_t qv[4];
#pragma unroll
            for (int q = 0; q < 4; ++q) {
                int r32 = m * 16 + (lane >> 2) + ((q & 1) ? 8 : 0);
                int k = w * 128 + t * 16 + (lane & 3) * 2 + ((q >= 2) ? 8 : 0);
                float v0 = 0.f, v1 = 0.f;
                if (r32 < 24) {
                    int gate = r32 >> 3, jj = r32 & 7;
                    const float* src = W_hh + (size_t)(gate * H_ + c * 8 + jj) * H_ + k;
                    v0 = src[0]; v1 = src[1];
                }
                __nv_bfloat162 pv = __floats2bfloat162_rn(v0, v1);
                qv[q] = *(uint32_t*)&pv;
            }
            g_wfrag[(size_t)c * 4096 + li] = make_uint4(qv[0], qv[1], qv[2], qv[3]);
        }
    } else if (bid < PREP_CVTE0) {
        int t = bid - PREP_EMBED0;
        if (tid < 128) {
            int tok = x[t];
            float4 v = ((const float4*)(emb_W + (size_t)tok * E_))[tid];
            __nv_bfloat162* d = (__nv_bfloat162*)(g_featbf + (size_t)t * F_ + H_) + 2 * tid;
            d[0] = __floats2bfloat162_rn(v.x, v.y);
            d[1] = __floats2bfloat162_rn(v.z, v.w);
        }
    } else if (bid < PREP_CVTL0) {
        int i = (bid - PREP_CVTE0) * 256 + tid;
        float4 v = ((const float4*)emb_W)[i];
        ((__nv_bfloat162*)g_embh)[2 * i]     = __floats2bfloat162_rn(v.x, v.y);
        ((__nv_bfloat162*)g_embh)[2 * i + 1] = __floats2bfloat162_rn(v.z, v.w);
    } else if (bid < PREP_CVTW0) {
        int i = (bid - PREP_CVTL0) * 256 + tid;
        float4 v = ((const float4*)lin_W)[i];
        ((__nv_bfloat162*)g_linbf)[2 * i]     = __floats2bfloat162_rn(v.x, v.y);
        ((__nv_bfloat162*)g_linbf)[2 * i + 1] = __floats2bfloat162_rn(v.z, v.w);
    } else {
        int i = (bid - PREP_CVTW0) * 256 + tid;
        float4 v = ((const float4*)W_ih)[i];
        ((__nv_bfloat162*)g_wihbf)[2 * i]     = __floats2bfloat162_rn(v.x, v.y);
        ((__nv_bfloat162*)g_wihbf)[2 * i + 1] = __floats2bfloat162_rn(v.z, v.w);
    }
}

// ---------------- K3: persistent GRU (HMMA GEMV + store/sweep grid barrier) ----------------
__global__ void __launch_bounds__(256, 1) gru_kernel(const int* __restrict__ x,
                                                     const float* __restrict__ b_hh) {
    __shared__ uint32_t h_s[8 * LDKW];      // bf16x2 [b][k/2 padded] ~16.5KB
    __shared__ float red[8 * 32 * 8];       // [w][row32][b] 8KB
    __shared__ float gh_s[24 * 8];
    const int c = blockIdx.x, tid = threadIdx.x;
    const int w = tid >> 5, lane = tid & 31;
    const int j0 = c * 8;
    const int jj = tid >> 3, bb = tid & 7;  // gate threads (tid<64)
    const int j = j0 + jj;
    float bh0 = 0.f, bh1 = 0.f, bh2 = 0.f, hreg = 0.f;
    if (tid < 64) { bh0 = b_hh[j]; bh1 = b_hh[H_ + j]; bh2 = b_hh[2 * H_ + j]; }

    unsigned int* arr;
    asm("mov.u64 %0, g_arr;" : "=l"(arr));
    const uint4* wf = g_wfrag + (size_t)c * 4096 + (w << 9) + lane;   // + (t*2+m)*32

    for (int s = 0; s < S_; ++s) {
        const int p = s & 1;

        // prefetch gx / mask (gate threads)
        float xr = 0.f, xz = 0.f, xn = 0.f;
        int msk = 0, tix = 0;
        if (tid < 64) {
            tix = bb * S_ + s;
            const float* gxr = g_gx + (size_t)tix * G_;
            xr = __ldcg(gxr + j);
            xz = __ldcg(gxr + H_ + j);
            xn = __ldcg(gxr + 2 * H_ + j);
            msk = (__ldg(x + tix) == 0);           // PAD
        }

        if (s == 0) {
            if (tid < 192) gh_s[tid] = 0.f;        // h == 0 -> gh == 0
            __syncthreads();
        } else {
            // load h (bf16) into padded smem — vectorized 16B loads
            const uint4* src = (const uint4*)((const uint32_t*)g_hbuf16 + p * (8 * 512));
#pragma unroll
            for (int r = 0; r < 4; ++r) {
                int i4 = tid + r * 256;            // uint4 index, 0..1023
                int w0 = i4 * 4;
                int b = w0 >> 9, kw = w0 & 511;
                *(uint4*)(h_s + b * LDKW + kw) = __ldcg(src + i4);
            }
            __syncthreads();

            // HMMA GEMV: D[32 gate rows][8 b] partial over this warp's K slice (128)
            float acc[2][4] = {{0.f, 0.f, 0.f, 0.f}, {0.f, 0.f, 0.f, 0.f}};
            const uint32_t* hb = h_s + (lane >> 2) * LDKW + w * 64 + (lane & 3);
#pragma unroll
            for (int t = 0; t < 8; ++t) {
                uint32_t b0 = hb[t * 8];
                uint32_t b1 = hb[t * 8 + 4];
                uint4 a0 = wf[(t * 2 + 0) * 32];
                uint4 a1 = wf[(t * 2 + 1) * 32];
                uint32_t A0[4] = {a0.x, a0.y, a0.z, a0.w};
                uint32_t A1[4] = {a1.x, a1.y, a1.z, a1.w};
                mma16816(acc[0], A0, b0, b1);
                mma16816(acc[1], A1, b0, b1);
            }
            {
                int row = lane >> 2, col = (lane & 3) * 2;
                float* base = red + (size_t)w * 256;
                *(float2*)(base + (row +  0) * 8 + col) = make_float2(acc[0][0], acc[0][1]);
                *(float2*)(base + (row +  8) * 8 + col) = make_float2(acc[0][2], acc[0][3]);
                *(float2*)(base + (row + 16) * 8 + col) = make_float2(acc[1][0], acc[1][1]);
                *(float2*)(base + (row + 24) * 8 + col) = make_float2(acc[1][2], acc[1][3]);
            }
            __syncthreads();
            if (tid < 192) {
                int r = tid % 24, b = tid / 24;
                float v = 0.f;
#pragma unroll
                for (int q = 0; q < 8; ++q) v += red[(q * 32 + r) * 8 + b];
                gh_s[r * 8 + b] = v;
            }
            __syncthreads();
        }

        if (tid < 64) {
            float hr = gh_s[(0 * 8 + jj) * 8 + bb] + bh0;
            float hz = gh_s[(1 * 8 + jj) * 8 + bb] + bh1;
            float hn = gh_s[(2 * 8 + jj) * 8 + bb] + bh2;
            float r = 1.f / (1.f + __expf(-(xr + hr)));
            float z = 1.f / (1.f + __expf(-(xz + hz)));
            float n = tanhf(xn + r * hn);
            float hnew = (1.f - z) * n + z * hreg;
            float hout = msk ? hreg : hnew;
            hreg = hout;                                         // fp32 state in register
            g_hbuf16[(p ^ 1) * (B_ * H_) + bb * H_ + j] = __float2bfloat16(hout);
            g_featbf[(size_t)tix * F_ + j] = __float2bfloat16(msk ? 0.f : hout);
        }
        if (s < S_ - 1) {
            __syncthreads();                    // all h-stores of this CTA done
            // arrive: one release store to own 128B-spread slot (no RMW serialization)
            if (tid == 0)
                asm volatile("st.release.gpu.global.u32 [%0], %1;"
                             :: "l"(arr + (size_t)c * 32), "r"((unsigned)(s + 1)) : "memory");
            // wait: every CTA sweeps all slots in parallel (single hop)
            bool ok;
            do {
                unsigned int v = 0u;
                if (tid < GRU_CTAS)
                    asm volatile("ld.acquire.gpu.global.u32 %0, [%1];"
                                 : "=r"(v) : "l"(arr + (size_t)tid * 32) : "memory");
                ok = __syncthreads_and((tid >= GRU_CTAS) || (v > (unsigned)s));
            } while (!ok);
        }
    }
}

// ---------------- HMMA bf16 GEMM template ----------------
// C = A[M,K(lda)] @ B[N,K(ldb)]^T
// EPI 0: tanh(acc+bias)->bf16.  EPI 1: fp32 + softmax partials.  EPI 2: acc+bias->fp32.
#define LDP_ 72   // padded row length (bf16): 144B rows, LDSM conflict-free

template <int EPI>
__global__ void __launch_bounds__(256) hmma_kernel(
    const __nv_bfloat16* __restrict__ Abf, int lda,
    const __nv_bfloat16* __restrict__ Bbf, int ldb, int K,
    const float* __restrict__ bias,
    __nv_bfloat16* __restrict__ outb, int ldob,
    float* __restrict__ outf, int ldof, float2* __restrict__ part)
{
    __shared__ __nv_bfloat16 As[128 * LDP_];
    __shared__ __nv_bfloat16 Bs[128 * LDP_];
    const uint32_t sA = smem_u32(As), sB = smem_u32(Bs);
    const int tid = threadIdx.x, wid = tid >> 5, lane = tid & 31;
    const int m0 = blockIdx.y * 128, n0 = blockIdx.x * 128;
    const int mi = wid >> 1, nj = wid & 1;
    const int qr = lane >> 2, qc = lane & 3;

    const int lrowA = lane & 15, lkA = (lane >> 4) * 8;
    const int lrowB = (lane & 7) + ((lane >> 4) << 3), lkB = ((lane >> 3) & 1) * 8;

    float acc[2][8][4];
#pragma unroll
    for (int ms = 0; ms < 2; ++ms)
#pragma unroll
        for (int ns = 0; ns < 8; ++ns)
#pragma unroll
            for (int q = 0; q < 4; ++q) acc[ms][ns][q] = 0.f;

    for (int k0 = 0; k0 < K; k0 += 64) {
#pragma unroll
        for (int i = 0; i < 4; ++i) {
            int u = tid + i * 256;
            int r = u >> 3, c = u & 7;
            *(uint4*)(As + r * LDP_ + c * 8) =
                *(const uint4*)(Abf + (size_t)(m0 + r) * lda + k0 + c * 8);
            *(uint4*)(Bs + r * LDP_ + c * 8) =
                *(const uint4*)(Bbf + (size_t)(n0 + r) * ldb + k0 + c * 8);
        }
        __syncthreads();
#pragma unroll
        for (int kk = 0; kk < 64; kk += 16) {
            uint32_t a[2][4];
#pragma unroll
            for (int ms = 0; ms < 2; ++ms)
                ldsm4(a[ms][0], a[ms][1], a[ms][2], a[ms][3],
                      sA + (uint32_t)((mi * 32 + ms * 16 + lrowA) * LDP_ + kk + lkA) * 2);
            uint32_t bf[8][2];
#pragma unroll
            for (int np = 0; np < 4; ++np) {
                uint32_t r0, r1, r2, r3;
                ldsm4(r0, r1, r2, r3,
                      sB + (uint32_t)((nj * 64 + np * 16 + lrowB) * LDP_ + kk + lkB) * 2);
                bf[np * 2 + 0][0] = r0; bf[np * 2 + 0][1] = r1;
                bf[np * 2 + 1][0] = r2; bf[np * 2 + 1][1] = r3;
            }
#pragma unroll
            for (int ns = 0; ns < 8; ++ns) {
                mma16816(acc[0][ns], a[0], bf[ns][0], bf[ns][1]);
                mma16816(acc[1][ns], a[1], bf[ns][0], bf[ns][1]);
            }
        }
        __syncthreads();
    }

    const int colbase = n0 + nj * 64;
#pragma unroll
    for (int ms = 0; ms < 2; ++ms) {
#pragma unroll
        for (int half = 0; half < 2; ++half) {
            int row = m0 + mi * 32 + ms * 16 + half * 8 + qr;
            if (EPI == 0) {
#pragma unroll
                for (int ns = 0; ns < 8; ++ns) {
                    int col = colbase + ns * 8 + qc * 2;
                    float v0 = tanhf(acc[ms][ns][half * 2 + 0] + bias[col]);
                    float v1 = tanhf(acc[ms][ns][half * 2 + 1] + bias[col + 1]);
                    *(__nv_bfloat162*)(outb + (size_t)row * ldob + col) =
                        __floats2bfloat162_rn(v0, v1);
                }
            } else if (EPI == 2) {
#pragma unroll
                for (int ns = 0; ns < 8; ++ns) {
                    int col = colbase + ns * 8 + qc * 2;
                    float v0 = acc[ms][ns][half * 2 + 0] + bias[col];
                    float v1 = acc[ms][ns][half * 2 + 1] + bias[col + 1];
                    *(float2*)(outf + (size_t)row * ldof + col) = make_float2(v0, v1);
                }
            } else {
                float* op = outf + (size_t)row * ldof + colbase + qc * 2;
                float mx = -1e30f;
#pragma unroll
                for (int ns = 0; ns < 8; ++ns) {
                    float v0 = acc[ms][ns][half * 2 + 0];
                    float v1 = acc[ms][ns][half * 2 + 1];
                    *(float2*)(op + ns * 8) = make_float2(v0, v1);
                    mx = fmaxf(mx, fmaxf(v0, v1));
                }
                mx = fmaxf(mx, __shfl_xor_sync(0xffffffffu, mx, 1));
                mx = fmaxf(mx, __shfl_xor_sync(0xffffffffu, mx, 2));
                float sm = 0.f;
#pragma unroll
                for (int ns = 0; ns < 8; ++ns) {
                    sm += __expf(acc[ms][ns][half * 2 + 0] - mx);
                    sm += __expf(acc[ms][ns][half * 2 + 1] - mx);
                }
                sm += __shfl_xor_sync(0xffffffffu, sm, 1);
                sm += __shfl_xor_sync(0xffffffffu, sm, 2);
                if (qc == 0)
                    part[(size_t)row * NT2_ + blockIdx.x * 2 + nj] = make_float2(mx, sm);
            }
        }
    }
}

// ---------------- K6: combine partials -> lse ----------------
__global__ void lse_kernel() {
    int row = blockIdx.x, lane = threadIdx.x;
    float m = -1e30f, s = 0.f;
    for (int i = lane; i < NT2_; i += 32) {
        float2 p = g_part[(size_t)row * NT2_ + i];
        if (p.x > m) { s = s * __expf(m - p.x) + p.y; m = p.x; }
        else         { s = s + p.y * __expf(p.x - m); }
    }
#pragma unroll
    for (int o = 16; o > 0; o >>= 1) {
        float mo = __shfl_xor_sync(0xffffffffu, m, o);
        float so = __shfl_xor_sync(0xffffffffu, s, o);
        if (mo > m) { s = s * __expf(m - mo) + so; m = mo; }
        else        { s = s + so * __expf(mo - m); }
    }
    if (lane == 0) g_lse[row] = m + logf(s);
}

// ---------------- K7: out -= lse[row] ----------------
__global__ void sub_kernel(float* __restrict__ out) {
    size_t idx = (size_t)blockIdx.x * 256 + threadIdx.x;
    int row = (int)(idx / (V_ / 4));
    float4 v = ((float4*)out)[idx];
    float l = g_lse[row];
    v.x -= l; v.y -= l; v.z -= l; v.w -= l;
    ((float4*)out)[idx] = v;
}

// ---------------- launch ----------------
extern "C" void kernel_launch(void* const* d_in, const int* in_sizes, int n_in,
                              void* d_out, int out_size) {
    const int*   x     = (const int*)d_in[0];
    const float* emb_W = (const float*)d_in[1];
    const float* W_ih  = (const float*)d_in[2];
    const float* W_hh  = (const float*)d_in[3];
    const float* b_ih  = (const float*)d_in[4];
    const float* b_hh  = (const float*)d_in[5];
    const float* lin_W = (const float*)d_in[6];
    const float* lin_b = (const float*)d_in[7];
    float* out = (float*)d_out;

    float* gx;
    __nv_bfloat16 *featbf, *embh, *linbf, *wihbf, *logbf;
    float2* part;
    cudaGetSymbolAddress((void**)&featbf, g_featbf);
    cudaGetSymbolAddress((void**)&gx,     g_gx);
    cudaGetSymbolAddress((void**)&embh,   g_embh);
    cudaGetSymbolAddress((void**)&linbf,  g_linbf);
    cudaGetSymbolAddress((void**)&wihbf,  g_wihbf);
    cudaGetSymbolAddress((void**)&logbf,  g_logbf);
    cudaGetSymbolAddress((void**)&part,   g_part);

    // 1: fused prep (pack W_hh fragments + embed + cvt tables)
    prep_kernel<<<PREP_BLOCKS, 256>>>(W_hh, x, emb_W, lin_W, W_ih);
    // 2: gx = emb_bf16 @ W_ih_bf16^T + b_ih  (HMMA, fp32 out)
    hmma_kernel<2><<<dim3(G_ / 128, T_ / 128), 256>>>(featbf + H_, F_, wihbf, E_, E_,
                                                      b_ih, nullptr, 0, gx, G_, nullptr);
    // 3: GRU recurrence (HMMA GEMV, store/sweep barrier)
    gru_kernel<<<GRU_CTAS, 256>>>(x, b_hh);
    // 4: logits = tanh(featbf @ linbf^T + lin_b) -> bf16   [profiled]
    hmma_kernel<0><<<dim3(E_ / 128, T_ / 128), 256>>>(featbf, F_, linbf, F_, F_,
                                                      lin_b, logbf, E_, nullptr, 0, nullptr);
    // 5: scores + fused softmax partials
    hmma_kernel<1><<<dim3(NT_, T_ / 128), 256>>>(logbf, E_, embh, E_, E_,
                                                 nullptr, nullptr, 0, out, V_, part);
    // 6, 7
    lse_kernel<<<T_, 32>>>();
    sub_kernel<<<(T_ * (V_ / 4)) / 256, 256>>>(out);
}

// round 14
// speedup vs baseline: 1.0374x; 1.0374x over previous
#include <cuda_runtime.h>
#include <cuda_bf16.h>
#include <math.h>
#include <cstdint>

#define B_ 8
#define S_ 256
#define V_ 32000
#define E_ 512
#define H_ 1024
#define G_ 3072      // 3H
#define T_ 2048      // B*S
#define F_ 1536      // H+E
#define NT_ 250      // V/128 score tiles per row
#define NT2_ 500     // per-row softmax partials
#define GRU_CTAS 128
#define LDKW 516     // u32 words per batch row in h_s (1032 bf16, bank-spread)

// ---------------- scratch (static device globals; no allocation) ----------------
__device__ uint4 g_wfrag[(size_t)GRU_CTAS * 4096];       // W_hh bf16 MMA A-fragments, 64KB/CTA
__device__ __nv_bfloat16 g_featbf[(size_t)T_ * F_];      // bf16 feat: ctx | emb
__device__ float g_gx[(size_t)T_ * G_];                  // input gates (fp32)
__device__ __nv_bfloat16 g_embh[(size_t)V_ * E_];        // emb table bf16
__device__ __nv_bfloat16 g_linbf[(size_t)E_ * F_];       // lin_W bf16
__device__ __nv_bfloat16 g_wihbf[(size_t)G_ * E_];       // W_ih bf16
__device__ __nv_bfloat16 g_logbf[(size_t)T_ * E_];       // logits bf16
__device__ float2 g_part[(size_t)T_ * NT2_];             // (max, sumexp) partials
__device__ float g_lse[T_];
__device__ __nv_bfloat16 g_hbuf16[2 * B_ * H_];          // ping-pong h exchange, bf16 [b][k]
__device__ unsigned int g_cnt8[8 * 64];                  // 8 sharded barrier counters, 256B apart

// ---------------- helpers ----------------
__device__ __forceinline__ uint32_t smem_u32(const void* p) {
    uint32_t a;
    asm("{ .reg .u64 t; cvta.to.shared.u64 t, %1; cvt.u32.u64 %0, t; }" : "=r"(a) : "l"(p));
    return a;
}
__device__ __forceinline__ void ldsm4(uint32_t& r0, uint32_t& r1, uint32_t& r2, uint32_t& r3,
                                      uint32_t addr) {
    asm volatile("ldmatrix.sync.aligned.m8n8.x4.shared.b16 {%0,%1,%2,%3}, [%4];"
                 : "=r"(r0), "=r"(r1), "=r"(r2), "=r"(r3) : "r"(addr));
}
__device__ __forceinline__ void mma16816(float* c, const uint32_t* a, uint32_t b0, uint32_t b1) {
    asm volatile(
        "mma.sync.aligned.m16n8k16.row.col.f32.bf16.bf16.f32 "
        "{%0,%1,%2,%3}, {%4,%5,%6,%7}, {%8,%9}, {%0,%1,%2,%3};"
        : "+f"(c[0]), "+f"(c[1]), "+f"(c[2]), "+f"(c[3])
        : "r"(a[0]), "r"(a[1]), "r"(a[2]), "r"(a[3]), "r"(b0), "r"(b1));
}

// ---------------- K1: fused prep ----------------
#define PREP_EMBED0   GRU_CTAS                              // 128
#define PREP_CVTE0    (PREP_EMBED0 + T_)                    // 2176
#define PREP_CVTL0    (PREP_CVTE0 + (V_ * E_ / 4) / 256)    // 18176
#define PREP_CVTW0    (PREP_CVTL0 + (E_ * F_ / 4) / 256)    // 18944
#define PREP_BLOCKS   (PREP_CVTW0 + (G_ * E_ / 4) / 256)    // 20480

__global__ void __launch_bounds__(256) prep_kernel(
    const float* __restrict__ W_hh, const int* __restrict__ x,
    const float* __restrict__ emb_W, const float* __restrict__ lin_W,
    const float* __restrict__ W_ih)
{
    const int bid = blockIdx.x, tid = threadIdx.x;
    if (bid < PREP_EMBED0) {
        // ---- pack W_hh into mma.m16n8k16 A-fragments (bf16) for CTA c ----
        int c = bid;
        if (c == 0 && tid < 8 * 64) g_cnt8[tid] = 0u;
        for (int it = 0; it < 16; ++it) {
            int li = it * 256 + tid;              // uint4 index within this CTA's block
            int w = li >> 9, rest = li & 511;
            int t = rest >> 6, rest2 = rest & 63;
            int m = rest2 >> 5, lane = rest2 & 31;
            uint32_t qv[4];
#pragma unroll
            for (int q = 0; q < 4; ++q) {
                int r32 = m * 16 + (lane >> 2) + ((q & 1) ? 8 : 0);
                int k = w * 128 + t * 16 + (lane & 3) * 2 + ((q >= 2) ? 8 : 0);
                float v0 = 0.f, v1 = 0.f;
                if (r32 < 24) {
                    int gate = r32 >> 3, jj = r32 & 7;
                    const float* src = W_hh + (size_t)(gate * H_ + c * 8 + jj) * H_ + k;
                    v0 = src[0]; v1 = src[1];
                }
                __nv_bfloat162 pv = __floats2bfloat162_rn(v0, v1);
                qv[q] = *(uint32_t*)&pv;
            }
            g_wfrag[(size_t)c * 4096 + li] = make_uint4(qv[0], qv[1], qv[2], qv[3]);
        }
    } else if (bid < PREP_CVTE0) {
        int t = bid - PREP_EMBED0;
        if (tid < 128) {
            int tok = x[t];
            float4 v = ((const float4*)(emb_W + (size_t)tok * E_))[tid];
            __nv_bfloat162* d = (__nv_bfloat162*)(g_featbf + (size_t)t * F_ + H_) + 2 * tid;
            d[0] = __floats2bfloat162_rn(v.x, v.y);
            d[1] = __floats2bfloat162_rn(v.z, v.w);
        }
    } else if (bid < PREP_CVTL0) {
        int i = (bid - PREP_CVTE0) * 256 + tid;
        float4 v = ((const float4*)emb_W)[i];
        ((__nv_bfloat162*)g_embh)[2 * i]     = __floats2bfloat162_rn(v.x, v.y);
        ((__nv_bfloat162*)g_embh)[2 * i + 1] = __floats2bfloat162_rn(v.z, v.w);
    } else if (bid < PREP_CVTW0) {
        int i = (bid - PREP_CVTL0) * 256 + tid;
        float4 v = ((const float4*)lin_W)[i];
        ((__nv_bfloat162*)g_linbf)[2 * i]     = __floats2bfloat162_rn(v.x, v.y);
        ((__nv_bfloat162*)g_linbf)[2 * i + 1] = __floats2bfloat162_rn(v.z, v.w);
    } else {
        int i = (bid - PREP_CVTW0) * 256 + tid;
        float4 v = ((const float4*)W_ih)[i];
        ((__nv_bfloat162*)g_wihbf)[2 * i]     = __floats2bfloat162_rn(v.x, v.y);
        ((__nv_bfloat162*)g_wihbf)[2 * i + 1] = __floats2bfloat162_rn(v.z, v.w);
    }
}

// ---------------- K3: persistent GRU (HMMA GEMV + 8-way sharded barrier) ----------------
__global__ void __launch_bounds__(256, 1) gru_kernel(const int* __restrict__ x,
                                                     const float* __restrict__ b_hh) {
    __shared__ uint32_t h_s[8 * LDKW];      // bf16x2 [b][k/2 padded] ~16.5KB
    __shared__ float red[8 * 32 * 8];       // [w][row32][b] 8KB
    __shared__ float gh_s[24 * 8];
    const int c = blockIdx.x, tid = threadIdx.x;
    const int w = tid >> 5, lane = tid & 31;
    const int j0 = c * 8;
    const int jj = tid >> 3, bb = tid & 7;  // gate threads (tid<64)
    const int j = j0 + jj;
    float bh0 = 0.f, bh1 = 0.f, bh2 = 0.f, hreg = 0.f;
    if (tid < 64) { bh0 = b_hh[j]; bh1 = b_hh[H_ + j]; bh2 = b_hh[2 * H_ + j]; }

    unsigned int* cnt8;
    asm("mov.u64 %0, g_cnt8;" : "=l"(cnt8));
    const uint4* wf = g_wfrag + (size_t)c * 4096 + (w << 9) + lane;   // + (t*2+m)*32

    // prefetch step-0 gx / mask (gate threads)
    float xr = 0.f, xz = 0.f, xn = 0.f;
    int msk = 0, tix = 0;
    if (tid < 64) {
        tix = bb * S_;
        const float* gxr = g_gx + (size_t)tix * G_;
        xr = __ldcg(gxr + j);
        xz = __ldcg(gxr + H_ + j);
        xn = __ldcg(gxr + 2 * H_ + j);
        msk = (__ldg(x + tix) == 0);
    }

    for (int s = 0; s < S_; ++s) {
        const int p = s & 1;

        if (s == 0) {
            if (tid < 192) gh_s[tid] = 0.f;        // h == 0 -> gh == 0
            __syncthreads();
        } else {
            // load h (bf16) into padded smem — vectorized 16B loads
            const uint4* src = (const uint4*)((const uint32_t*)g_hbuf16 + p * (8 * 512));
#pragma unroll
            for (int r = 0; r < 4; ++r) {
                int i4 = tid + r * 256;            // uint4 index, 0..1023
                int w0 = i4 * 4;
                int b = w0 >> 9, kw = w0 & 511;
                *(uint4*)(h_s + b * LDKW + kw) = __ldcg(src + i4);
            }
            __syncthreads();

            // HMMA GEMV: D[32 gate rows][8 b] partial over this warp's K slice (128)
            float acc[2][4] = {{0.f, 0.f, 0.f, 0.f}, {0.f, 0.f, 0.f, 0.f}};
            const uint32_t* hb = h_s + (lane >> 2) * LDKW + w * 64 + (lane & 3);
#pragma unroll
            for (int t = 0; t < 8; ++t) {
                uint32_t b0 = hb[t * 8];
                uint32_t b1 = hb[t * 8 + 4];
                uint4 a0 = wf[(t * 2 + 0) * 32];
                uint4 a1 = wf[(t * 2 + 1) * 32];
                uint32_t A0[4] = {a0.x, a0.y, a0.z, a0.w};
                uint32_t A1[4] = {a1.x, a1.y, a1.z, a1.w};
                mma16816(acc[0], A0, b0, b1);
                mma16816(acc[1], A1, b0, b1);
            }
            {
                int row = lane >> 2, col = (lane & 3) * 2;
                float* base = red + (size_t)w * 256;
                *(float2*)(base + (row +  0) * 8 + col) = make_float2(acc[0][0], acc[0][1]);
                *(float2*)(base + (row +  8) * 8 + col) = make_float2(acc[0][2], acc[0][3]);
                *(float2*)(base + (row + 16) * 8 + col) = make_float2(acc[1][0], acc[1][1]);
                *(float2*)(base + (row + 24) * 8 + col) = make_float2(acc[1][2], acc[1][3]);
            }
            __syncthreads();
            if (tid < 192) {
                int r = tid % 24, b = tid / 24;
                float v = 0.f;
#pragma unroll
                for (int q = 0; q < 8; ++q) v += red[(q * 32 + r) * 8 + b];
                gh_s[r * 8 + b] = v;
            }
            __syncthreads();
        }

        if (tid < 64) {
            float hr = gh_s[(0 * 8 + jj) * 8 + bb] + bh0;
            float hz = gh_s[(1 * 8 + jj) * 8 + bb] + bh1;
            float hn = gh_s[(2 * 8 + jj) * 8 + bb] + bh2;
            float r = 1.f / (1.f + __expf(-(xr + hr)));
            float z = 1.f / (1.f + __expf(-(xz + hz)));
            float n = tanhf(xn + r * hn);
            float hnew = (1.f - z) * n + z * hreg;
            float hout = msk ? hreg : hnew;
            hreg = hout;                                         // fp32 state in register
            g_hbuf16[(p ^ 1) * (B_ * H_) + bb * H_ + j] = __float2bfloat16(hout);
            g_featbf[(size_t)tix * F_ + j] = __float2bfloat16(msk ? 0.f : hout);
        }

        if (s < S_ - 1) {
            // prefetch next step's gx / mask (loads land during the barrier poll)
            if (tid < 64) {
                tix = bb * S_ + (s + 1);
                const float* gxr = g_gx + (size_t)tix * G_;
                xr = __ldcg(gxr + j);
                xz = __ldcg(gxr + H_ + j);
                xn = __ldcg(gxr + 2 * H_ + j);
                msk = (__ldg(x + tix) == 0);
            }
            __syncthreads();                    // all h-stores of this CTA done
            // arrive: 8-way sharded counters (16 CTAs each, 256B apart -> distinct LTS)
            if (tid == 0)
                asm volatile("red.release.gpu.global.add.u32 [%0], 1;"
                             :: "l"(cnt8 + (c & 7) * 64) : "memory");
            // wait: 8 threads poll the 8 counters
            const unsigned target = 16u * (unsigned)(s + 1);
            bool ok;
            do {
                unsigned int v = target;
                if (tid < 8)
                    asm volatile("ld.acquire.gpu.global.u32 %0, [%1];"
                                 : "=r"(v) : "l"(cnt8 + tid * 64) : "memory");
                ok = __syncthreads_and(v >= target);
            } while (!ok);
        }
    }
}

// ---------------- HMMA bf16 GEMM template ----------------
// C = A[M,K(lda)] @ B[N,K(ldb)]^T
// EPI 0: tanh(acc+bias)->bf16.  EPI 1: fp32 + softmax partials.  EPI 2: acc+bias->fp32.
#define LDP_ 72   // padded row length (bf16): 144B rows, LDSM conflict-free

template <int EPI>
__global__ void __launch_bounds__(256) hmma_kernel(
    const __nv_bfloat16* __restrict__ Abf, int lda,
    const __nv_bfloat16* __restrict__ Bbf, int ldb, int K,
    const float* __restrict__ bias,
    __nv_bfloat16* __restrict__ outb, int ldob,
    float* __restrict__ outf, int ldof, float2* __restrict__ part)
{
    __shared__ __nv_bfloat16 As[128 * LDP_];
    __shared__ __nv_bfloat16 Bs[128 * LDP_];
    const uint32_t sA = smem_u32(As), sB = smem_u32(Bs);
    const int tid = threadIdx.x, wid = tid >> 5, lane = tid & 31;
    const int m0 = blockIdx.y * 128, n0 = blockIdx.x * 128;
    const int mi = wid >> 1, nj = wid & 1;
    const int qr = lane >> 2, qc = lane & 3;

    const int lrowA = lane & 15, lkA = (lane >> 4) * 8;
    const int lrowB = (lane & 7) + ((lane >> 4) << 3), lkB = ((lane >> 3) & 1) * 8;

    float acc[2][8][4];
#pragma unroll
    for (int ms = 0; ms < 2; ++ms)
#pragma unroll
        for (int ns = 0; ns < 8; ++ns)
#pragma unroll
            for (int q = 0; q < 4; ++q) acc[ms][ns][q] = 0.f;

    for (int k0 = 0; k0 < K; k0 += 64) {
#pragma unroll
        for (int i = 0; i < 4; ++i) {
            int u = tid + i * 256;
            int r = u >> 3, c = u & 7;
            *(uint4*)(As + r * LDP_ + c * 8) =
                *(const uint4*)(Abf + (size_t)(m0 + r) * lda + k0 + c * 8);
            *(uint4*)(Bs + r * LDP_ + c * 8) =
                *(const uint4*)(Bbf + (size_t)(n0 + r) * ldb + k0 + c * 8);
        }
        __syncthreads();
#pragma unroll
        for (int kk = 0; kk < 64; kk += 16) {
            uint32_t a[2][4];
#pragma unroll
            for (int ms = 0; ms < 2; ++ms)
                ldsm4(a[ms][0], a[ms][1], a[ms][2], a[ms][3],
                      sA + (uint32_t)((mi * 32 + ms * 16 + lrowA) * LDP_ + kk + lkA) * 2);
            uint32_t bf[8][2];
#pragma unroll
            for (int np = 0; np < 4; ++np) {
                uint32_t r0, r1, r2, r3;
                ldsm4(r0, r1, r2, r3,
                      sB + (uint32_t)((nj * 64 + np * 16 + lrowB) * LDP_ + kk + lkB) * 2);
                bf[np * 2 + 0][0] = r0; bf[np * 2 + 0][1] = r1;
                bf[np * 2 + 1][0] = r2; bf[np * 2 + 1][1] = r3;
            }
#pragma unroll
            for (int ns = 0; ns < 8; ++ns) {
                mma16816(acc[0][ns], a[0], bf[ns][0], bf[ns][1]);
                mma16816(acc[1][ns], a[1], bf[ns][0], bf[ns][1]);
            }
        }
        __syncthreads();
    }

    const int colbase = n0 + nj * 64;
#pragma unroll
    for (int ms = 0; ms < 2; ++ms) {
#pragma unroll
        for (int half = 0; half < 2; ++half) {
            int row = m0 + mi * 32 + ms * 16 + half * 8 + qr;
            if (EPI == 0) {
#pragma unroll
                for (int ns = 0; ns < 8; ++ns) {
                    int col = colbase + ns * 8 + qc * 2;
                    float v0 = tanhf(acc[ms][ns][half * 2 + 0] + bias[col]);
                    float v1 = tanhf(acc[ms][ns][half * 2 + 1] + bias[col + 1]);
                    *(__nv_bfloat162*)(outb + (size_t)row * ldob + col) =
                        __floats2bfloat162_rn(v0, v1);
                }
            } else if (EPI == 2) {
#pragma unroll
                for (int ns = 0; ns < 8; ++ns) {
                    int col = colbase + ns * 8 + qc * 2;
                    float v0 = acc[ms][ns][half * 2 + 0] + bias[col];
                    float v1 = acc[ms][ns][half * 2 + 1] + bias[col + 1];
                    *(float2*)(outf + (size_t)row * ldof + col) = make_float2(v0, v1);
                }
            } else {
                float* op = outf + (size_t)row * ldof + colbase + qc * 2;
                float mx = -1e30f;
#pragma unroll
                for (int ns = 0; ns < 8; ++ns) {
                    float v0 = acc[ms][ns][half * 2 + 0];
                    float v1 = acc[ms][ns][half * 2 + 1];
                    *(float2*)(op + ns * 8) = make_float2(v0, v1);
                    mx = fmaxf(mx, fmaxf(v0, v1));
                }
                mx = fmaxf(mx, __shfl_xor_sync(0xffffffffu, mx, 1));
                mx = fmaxf(mx, __shfl_xor_sync(0xffffffffu, mx, 2));
                float sm = 0.f;
#pragma unroll
                for (int ns = 0; ns < 8; ++ns) {
                    sm += __expf(acc[ms][ns][half * 2 + 0] - mx);
                    sm += __expf(acc[ms][ns][half * 2 + 1] - mx);
                }
                sm += __shfl_xor_sync(0xffffffffu, sm, 1);
                sm += __shfl_xor_sync(0xffffffffu, sm, 2);
                if (qc == 0)
                    part[(size_t)row * NT2_ + blockIdx.x * 2 + nj] = make_float2(mx, sm);
            }
        }
    }
}

// ---------------- K6: combine partials -> lse ----------------
__global__ void lse_kernel() {
    int row = blockIdx.x, lane = threadIdx.x;
    float m = -1e30f, s = 0.f;
    for (int i = lane; i < NT2_; i += 32) {
        float2 p = g_part[(size_t)row * NT2_ + i];
        if (p.x > m) { s = s * __expf(m - p.x) + p.y; m = p.x; }
        else         { s = s + p.y * __expf(p.x - m); }
    }
#pragma unroll
    for (int o = 16; o > 0; o >>= 1) {
        float mo = __shfl_xor_sync(0xffffffffu, m, o);
        float so = __shfl_xor_sync(0xffffffffu, s, o);
        if (mo > m) { s = s * __expf(m - mo) + so; m = mo; }
        else        { s = s + so * __expf(mo - m); }
    }
    if (lane == 0) g_lse[row] = m + logf(s);
}

// ---------------- K7: out -= lse[row] ----------------
__global__ void sub_kernel(float* __restrict__ out) {
    size_t idx = (size_t)blockIdx.x * 256 + threadIdx.x;
    int row = (int)(idx / (V_ / 4));
    float4 v = ((float4*)out)[idx];
    float l = g_lse[row];
    v.x -= l; v.y -= l; v.z -= l; v.w -= l;
    ((float4*)out)[idx] = v;
}

// ---------------- launch ----------------
extern "C" void kernel_launch(void* const* d_in, const int* in_sizes, int n_in,
                              void* d_out, int out_size) {
    const int*   x     = (const int*)d_in[0];
    const float* emb_W = (const float*)d_in[1];
    const float* W_ih  = (const float*)d_in[2];
    const float* W_hh  = (const float*)d_in[3];
    const float* b_ih  = (const float*)d_in[4];
    const float* b_hh  = (const float*)d_in[5];
    const float* lin_W = (const float*)d_in[6];
    const float* lin_b = (const float*)d_in[7];
    float* out = (float*)d_out;

    float* gx;
    __nv_bfloat16 *featbf, *embh, *linbf, *wihbf, *logbf;
    float2* part;
    cudaGetSymbolAddress((void**)&featbf, g_featbf);
    cudaGetSymbolAddress((void**)&gx,     g_gx);
    cudaGetSymbolAddress((void**)&embh,   g_embh);
    cudaGetSymbolAddress((void**)&linbf,  g_linbf);
    cudaGetSymbolAddress((void**)&wihbf,  g_wihbf);
    cudaGetSymbolAddress((void**)&logbf,  g_logbf);
    cudaGetSymbolAddress((void**)&part,   g_part);

    // 1: fused prep (pack W_hh fragments + embed + cvt tables)
    prep_kernel<<<PREP_BLOCKS, 256>>>(W_hh, x, emb_W, lin_W, W_ih);
    // 2: gx = emb_bf16 @ W_ih_bf16^T + b_ih  (HMMA, fp32 out)
    hmma_kernel<2><<<dim3(G_ / 128, T_ / 128), 256>>>(featbf + H_, F_, wihbf, E_, E_,
                                                      b_ih, nullptr, 0, gx, G_, nullptr);
    // 3: GRU recurrence (HMMA GEMV, sharded barrier)
    gru_kernel<<<GRU_CTAS, 256>>>(x, b_hh);
    // 4: logits = tanh(featbf @ linbf^T + lin_b) -> bf16   [profiled]
    hmma_kernel<0><<<dim3(E_ / 128, T_ / 128), 256>>>(featbf, F_, linbf, F_, F_,
                                                      lin_b, logbf, E_, nullptr, 0, nullptr);
    // 5: scores + fused softmax partials
    hmma_kernel<1><<<dim3(NT_, T_ / 128), 256>>>(logbf, E_, embh, E_, E_,
                                                 nullptr, nullptr, 0, out, V_, part);
    // 6, 7
    lse_kernel<<<T_, 32>>>();
    sub_kernel<<<(T_ * (V_ / 4)) / 256, 256>>>(out);
}

// round 15
// speedup vs baseline: 1.0699x; 1.0314x over previous
#include <cuda_runtime.h>
#include <cuda_bf16.h>
#include <math.h>
#include <cstdint>

#define B_ 8
#define S_ 256
#define V_ 32000
#define E_ 512
#define H_ 1024
#define G_ 3072      // 3H
#define T_ 2048      // B*S
#define F_ 1536      // H+E
#define NT_ 250      // V/128 score tiles per row
#define NT2_ 500     // per-row softmax partials
#define GRU_CTAS 128
#define LDKW 516     // u32 words per batch row in h_s (1032 bf16, bank-spread)

// ---------------- scratch (static device globals; no allocation) ----------------
__device__ uint4 g_wfrag[(size_t)GRU_CTAS * 4096];       // W_hh bf16 MMA A-fragments, 64KB/CTA
__device__ __nv_bfloat16 g_featbf[(size_t)T_ * F_];      // bf16 feat: ctx | emb
__device__ float g_gx[(size_t)T_ * G_];                  // input gates (fp32)
__device__ __nv_bfloat16 g_embh[(size_t)V_ * E_];        // emb table bf16
__device__ __nv_bfloat16 g_linbf[(size_t)E_ * F_];       // lin_W bf16
__device__ __nv_bfloat16 g_wihbf[(size_t)G_ * E_];       // W_ih bf16
__device__ __nv_bfloat16 g_logbf[(size_t)T_ * E_];       // logits bf16
__device__ float2 g_part[(size_t)T_ * NT2_];             // (max, sumexp) partials
__device__ float g_lse[T_];
__device__ __nv_bfloat16 g_hbuf16[2 * B_ * H_];          // ping-pong h exchange, bf16 [b][k]
__device__ unsigned int g_cnt8[8 * 64];                  // 8 sharded barrier counters, 256B apart

// ---------------- helpers ----------------
__device__ __forceinline__ uint32_t smem_u32(const void* p) {
    uint32_t a;
    asm("{ .reg .u64 t; cvta.to.shared.u64 t, %1; cvt.u32.u64 %0, t; }" : "=r"(a) : "l"(p));
    return a;
}
__device__ __forceinline__ void cpasync16(uint32_t dst, const void* src) {
    asm volatile("cp.async.cg.shared.global [%0], [%1], 16;" :: "r"(dst), "l"(src));
}
#define CP_COMMIT()  asm volatile("cp.async.commit_group;" ::: "memory")
#define CP_WAIT(n)   asm volatile("cp.async.wait_group %0;" :: "n"(n) : "memory")
__device__ __forceinline__ void ldsm4(uint32_t& r0, uint32_t& r1, uint32_t& r2, uint32_t& r3,
                                      uint32_t addr) {
    asm volatile("ldmatrix.sync.aligned.m8n8.x4.shared.b16 {%0,%1,%2,%3}, [%4];"
                 : "=r"(r0), "=r"(r1), "=r"(r2), "=r"(r3) : "r"(addr));
}
__device__ __forceinline__ void mma16816(float* c, const uint32_t* a, uint32_t b0, uint32_t b1) {
    asm volatile(
        "mma.sync.aligned.m16n8k16.row.col.f32.bf16.bf16.f32 "
        "{%0,%1,%2,%3}, {%4,%5,%6,%7}, {%8,%9}, {%0,%1,%2,%3};"
        : "+f"(c[0]), "+f"(c[1]), "+f"(c[2]), "+f"(c[3])
        : "r"(a[0]), "r"(a[1]), "r"(a[2]), "r"(a[3]), "r"(b0), "r"(b1));
}

// ---------------- K1: fused prep ----------------
#define PREP_EMBED0   GRU_CTAS                              // 128
#define PREP_CVTE0    (PREP_EMBED0 + T_)                    // 2176
#define PREP_CVTL0    (PREP_CVTE0 + (V_ * E_ / 4) / 256)    // 18176
#define PREP_CVTW0    (PREP_CVTL0 + (E_ * F_ / 4) / 256)    // 18944
#define PREP_BLOCKS   (PREP_CVTW0 + (G_ * E_ / 4) / 256)    // 20480

__global__ void __launch_bounds__(256) prep_kernel(
    const float* __restrict__ W_hh, const int* __restrict__ x,
    const float* __restrict__ emb_W, const float* __restrict__ lin_W,
    const float* __restrict__ W_ih)
{
    const int bid = blockIdx.x, tid = threadIdx.x;
    if (bid < PREP_EMBED0) {
        // ---- pack W_hh into mma.m16n8k16 A-fragments (bf16) for CTA c ----
        int c = bid;
        if (c == 0 && tid < 8 * 64) g_cnt8[tid] = 0u;
        for (int it = 0; it < 16; ++it) {
            int li = it * 256 + tid;              // uint4 index within this CTA's block
            int w = li >> 9, rest = li & 511;
            int t = rest >> 6, rest2 = rest & 63;
            int m = rest2 >> 5, lane = rest2 & 31;
            uint32_t qv[4];
#pragma unroll
            for (int q = 0; q < 4; ++q) {
                int r32 = m * 16 + (lane >> 2) + ((q & 1) ? 8 : 0);
                int k = w * 128 + t * 16 + (lane & 3) * 2 + ((q >= 2) ? 8 : 0);
                float v0 = 0.f, v1 = 0.f;
                if (r32 < 24) {
                    int gate = r32 >> 3, jj = r32 & 7;
                    const float* src = W_hh + (size_t)(gate * H_ + c * 8 + jj) * H_ + k;
                    v0 = src[0]; v1 = src[1];
                }
                __nv_bfloat162 pv = __floats2bfloat162_rn(v0, v1);
                qv[q] = *(uint32_t*)&pv;
            }
            g_wfrag[(size_t)c * 4096 + li] = make_uint4(qv[0], qv[1], qv[2], qv[3]);
        }
    } else if (bid < PREP_CVTE0) {
        int t = bid - PREP_EMBED0;
        if (tid < 128) {
            int tok = x[t];
            float4 v = ((const float4*)(emb_W + (size_t)tok * E_))[tid];
            __nv_bfloat162* d = (__nv_bfloat162*)(g_featbf + (size_t)t * F_ + H_) + 2 * tid;
            d[0] = __floats2bfloat162_rn(v.x, v.y);
            d[1] = __floats2bfloat162_rn(v.z, v.w);
        }
    } else if (bid < PREP_CVTL0) {
        int i = (bid - PREP_CVTE0) * 256 + tid;
        float4 v = ((const float4*)emb_W)[i];
        ((__nv_bfloat162*)g_embh)[2 * i]     = __floats2bfloat162_rn(v.x, v.y);
        ((__nv_bfloat162*)g_embh)[2 * i + 1] = __floats2bfloat162_rn(v.z, v.w);
    } else if (bid < PREP_CVTW0) {
        int i = (bid - PREP_CVTL0) * 256 + tid;
        float4 v = ((const float4*)lin_W)[i];
        ((__nv_bfloat162*)g_linbf)[2 * i]     = __floats2bfloat162_rn(v.x, v.y);
        ((__nv_bfloat162*)g_linbf)[2 * i + 1] = __floats2bfloat162_rn(v.z, v.w);
    } else {
        int i = (bid - PREP_CVTW0) * 256 + tid;
        float4 v = ((const float4*)W_ih)[i];
        ((__nv_bfloat162*)g_wihbf)[2 * i]     = __floats2bfloat162_rn(v.x, v.y);
        ((__nv_bfloat162*)g_wihbf)[2 * i + 1] = __floats2bfloat162_rn(v.z, v.w);
    }
}

// ---------------- K3: persistent GRU (HMMA GEMV + 8-way sharded barrier) ----------------
__global__ void __launch_bounds__(256, 1) gru_kernel(const int* __restrict__ x,
                                                     const float* __restrict__ b_hh) {
    __shared__ uint32_t h_s[8 * LDKW];      // bf16x2 [b][k/2 padded] ~16.5KB
    __shared__ float red[8 * 32 * 8];       // [w][row32][b] 8KB
    __shared__ float gh_s[24 * 8];
    const int c = blockIdx.x, tid = threadIdx.x;
    const int w = tid >> 5, lane = tid & 31;
    const int j0 = c * 8;
    const int jj = tid >> 3, bb = tid & 7;  // gate threads (tid<64)
    const int j = j0 + jj;
    float bh0 = 0.f, bh1 = 0.f, bh2 = 0.f, hreg = 0.f;
    if (tid < 64) { bh0 = b_hh[j]; bh1 = b_hh[H_ + j]; bh2 = b_hh[2 * H_ + j]; }

    unsigned int* cnt8;
    asm("mov.u64 %0, g_cnt8;" : "=l"(cnt8));
    const uint4* wf = g_wfrag + (size_t)c * 4096 + (w << 9) + lane;   // + (t*2+m)*32

    // prefetch step-0 gx / mask (gate threads)
    float xr = 0.f, xz = 0.f, xn = 0.f;
    int msk = 0, tix = 0;
    if (tid < 64) {
        tix = bb * S_;
        const float* gxr = g_gx + (size_t)tix * G_;
        xr = __ldcg(gxr + j);
        xz = __ldcg(gxr + H_ + j);
        xn = __ldcg(gxr + 2 * H_ + j);
        msk = (__ldg(x + tix) == 0);
    }

    for (int s = 0; s < S_; ++s) {
        const int p = s & 1;

        if (s == 0) {
            if (tid < 192) gh_s[tid] = 0.f;        // h == 0 -> gh == 0
            __syncthreads();
        } else {
            // load h (bf16) into padded smem — vectorized 16B loads
            const uint4* src = (const uint4*)((const uint32_t*)g_hbuf16 + p * (8 * 512));
#pragma unroll
            for (int r = 0; r < 4; ++r) {
                int i4 = tid + r * 256;            // uint4 index, 0..1023
                int w0 = i4 * 4;
                int b = w0 >> 9, kw = w0 & 511;
                *(uint4*)(h_s + b * LDKW + kw) = __ldcg(src + i4);
            }
            __syncthreads();

            // HMMA GEMV: D[32 gate rows][8 b] partial over this warp's K slice (128)
            float acc[2][4] = {{0.f, 0.f, 0.f, 0.f}, {0.f, 0.f, 0.f, 0.f}};
            const uint32_t* hb = h_s + (lane >> 2) * LDKW + w * 64 + (lane & 3);
#pragma unroll
            for (int t = 0; t < 8; ++t) {
                uint32_t b0 = hb[t * 8];
                uint32_t b1 = hb[t * 8 + 4];
                uint4 a0 = wf[(t * 2 + 0) * 32];
                uint4 a1 = wf[(t * 2 + 1) * 32];
                uint32_t A0[4] = {a0.x, a0.y, a0.z, a0.w};
                uint32_t A1[4] = {a1.x, a1.y, a1.z, a1.w};
                mma16816(acc[0], A0, b0, b1);
                mma16816(acc[1], A1, b0, b1);
            }
            {
                int row = lane >> 2, col = (lane & 3) * 2;
                float* base = red + (size_t)w * 256;
                *(float2*)(base + (row +  0) * 8 + col) = make_float2(acc[0][0], acc[0][1]);
                *(float2*)(base + (row +  8) * 8 + col) = make_float2(acc[0][2], acc[0][3]);
                *(float2*)(base + (row + 16) * 8 + col) = make_float2(acc[1][0], acc[1][1]);
                *(float2*)(base + (row + 24) * 8 + col) = make_float2(acc[1][2], acc[1][3]);
            }
            __syncthreads();
            if (tid < 192) {
                int r = tid % 24, b = tid / 24;
                float v = 0.f;
#pragma unroll
                for (int q = 0; q < 8; ++q) v += red[(q * 32 + r) * 8 + b];
                gh_s[r * 8 + b] = v;
            }
            __syncthreads();
        }

        if (tid < 64) {
            float hr = gh_s[(0 * 8 + jj) * 8 + bb] + bh0;
            float hz = gh_s[(1 * 8 + jj) * 8 + bb] + bh1;
            float hn = gh_s[(2 * 8 + jj) * 8 + bb] + bh2;
            float r = 1.f / (1.f + __expf(-(xr + hr)));
            float z = 1.f / (1.f + __expf(-(xz + hz)));
            float n = tanhf(xn + r * hn);
            float hnew = (1.f - z) * n + z * hreg;
            float hout = msk ? hreg : hnew;
            hreg = hout;                                         // fp32 state in register
            g_hbuf16[(p ^ 1) * (B_ * H_) + bb * H_ + j] = __float2bfloat16(hout);
            g_featbf[(size_t)tix * F_ + j] = __float2bfloat16(msk ? 0.f : hout);
        }

        if (s < S_ - 1) {
            // prefetch next step's gx / mask (loads land during the barrier poll)
            if (tid < 64) {
                tix = bb * S_ + (s + 1);
                const float* gxr = g_gx + (size_t)tix * G_;
                xr = __ldcg(gxr + j);
                xz = __ldcg(gxr + H_ + j);
                xn = __ldcg(gxr + 2 * H_ + j);
                msk = (__ldg(x + tix) == 0);
            }
            __syncthreads();                    // all h-stores of this CTA done
            // arrive: 8-way sharded counters (16 CTAs each, 256B apart -> distinct LTS)
            if (tid == 0)
                asm volatile("red.release.gpu.global.add.u32 [%0], 1;"
                             :: "l"(cnt8 + (c & 7) * 64) : "memory");
            // wait: 8 threads poll the 8 counters
            const unsigned target = 16u * (unsigned)(s + 1);
            bool ok;
            do {
                unsigned int v = target;
                if (tid < 8)
                    asm volatile("ld.acquire.gpu.global.u32 %0, [%1];"
                                 : "=r"(v) : "l"(cnt8 + tid * 64) : "memory");
                ok = __syncthreads_and(v >= target);
            } while (!ok);
        }
    }
}

// ---------------- HMMA bf16 GEMM template (2-stage cp.async pipeline) ----------------
// C = A[M,K(lda)] @ B[N,K(ldb)]^T
// EPI 0: tanh(acc+bias)->bf16.  EPI 1: fp32 + softmax partials.  EPI 2: acc+bias->fp32.
#define LDP_ 72                         // padded row length (bf16): 144B rows, LDSM conflict-free
#define HSTG (128 * LDP_ * 2)           // 18432 B per matrix per stage
#define HSMEM (2 * 2 * HSTG)            // 2 stages x (A + B) = 73728 B

template <int EPI>
__global__ void __launch_bounds__(256) hmma_kernel(
    const __nv_bfloat16* __restrict__ Abf, int lda,
    const __nv_bfloat16* __restrict__ Bbf, int ldb, int K,
    const float* __restrict__ bias,
    __nv_bfloat16* __restrict__ outb, int ldob,
    float* __restrict__ outf, int ldof, float2* __restrict__ part)
{
    extern __shared__ char smem[];      // [stage][A|B]
    const uint32_t sb = smem_u32(smem);
    const int tid = threadIdx.x, wid = tid >> 5, lane = tid & 31;
    const int m0 = blockIdx.y * 128, n0 = blockIdx.x * 128;
    const int mi = wid >> 1, nj = wid & 1;
    const int qr = lane >> 2, qc = lane & 3;

    const int lrowA = lane & 15, lkA = (lane >> 4) * 8;
    const int lrowB = (lane & 7) + ((lane >> 4) << 3), lkB = ((lane >> 3) & 1) * 8;

    // issue one 64-wide K chunk (A + B tiles) into stage stg
    auto issue = [&](int k0, int stg) {
        const uint32_t base = sb + (uint32_t)stg * (2 * HSTG);
#pragma unroll
        for (int i = 0; i < 4; ++i) {
            int u = tid + i * 256;
            int r = u >> 3, c = u & 7;
            uint32_t soff = (uint32_t)(r * LDP_ + c * 8) * 2;
            cpasync16(base + soff,        Abf + (size_t)(m0 + r) * lda + k0 + c * 8);
            cpasync16(base + HSTG + soff, Bbf + (size_t)(n0 + r) * ldb + k0 + c * 8);
        }
        CP_COMMIT();
    };

    float acc[2][8][4];
#pragma unroll
    for (int ms = 0; ms < 2; ++ms)
#pragma unroll
        for (int ns = 0; ns < 8; ++ns)
#pragma unroll
            for (int q = 0; q < 4; ++q) acc[ms][ns][q] = 0.f;

    issue(0, 0);
    issue(64, 1);

    for (int k0 = 0; k0 < K; k0 += 64) {
        const int stg = (k0 >> 6) & 1;
        if (k0 + 64 < K) { CP_WAIT(1); }      // current chunk landed; next may be in flight
        else             { CP_WAIT(0); }
        __syncthreads();
        const uint32_t sA = sb + (uint32_t)stg * (2 * HSTG);
        const uint32_t sB = sA + HSTG;
#pragma unroll
        for (int kk = 0; kk < 64; kk += 16) {
            uint32_t a[2][4];
#pragma unroll
            for (int ms = 0; ms < 2; ++ms)
                ldsm4(a[ms][0], a[ms][1], a[ms][2], a[ms][3],
                      sA + (uint32_t)((mi * 32 + ms * 16 + lrowA) * LDP_ + kk + lkA) * 2);
            uint32_t bf[8][2];
#pragma unroll
            for (int np = 0; np < 4; ++np) {
                uint32_t r0, r1, r2, r3;
                ldsm4(r0, r1, r2, r3,
                      sB + (uint32_t)((nj * 64 + np * 16 + lrowB) * LDP_ + kk + lkB) * 2);
                bf[np * 2 + 0][0] = r0; bf[np * 2 + 0][1] = r1;
                bf[np * 2 + 1][0] = r2; bf[np * 2 + 1][1] = r3;
            }
#pragma unroll
            for (int ns = 0; ns < 8; ++ns) {
                mma16816(acc[0][ns], a[0], bf[ns][0], bf[ns][1]);
                mma16816(acc[1][ns], a[1], bf[ns][0], bf[ns][1]);
            }
        }
        __syncthreads();                      // stage stg fully consumed
        if (k0 + 128 < K) issue(k0 + 128, stg);
    }

    const int colbase = n0 + nj * 64;
#pragma unroll
    for (int ms = 0; ms < 2; ++ms) {
#pragma unroll
        for (int half = 0; half < 2; ++half) {
            int row = m0 + mi * 32 + ms * 16 + half * 8 + qr;
            if (EPI == 0) {
#pragma unroll
                for (int ns = 0; ns < 8; ++ns) {
                    int col = colbase + ns * 8 + qc * 2;
                    float v0 = tanhf(acc[ms][ns][half * 2 + 0] + bias[col]);
                    float v1 = tanhf(acc[ms][ns][half * 2 + 1] + bias[col + 1]);
                    *(__nv_bfloat162*)(outb + (size_t)row * ldob + col) =
                        __floats2bfloat162_rn(v0, v1);
                }
            } else if (EPI == 2) {
#pragma unroll
                for (int ns = 0; ns < 8; ++ns) {
                    int col = colbase + ns * 8 + qc * 2;
                    float v0 = acc[ms][ns][half * 2 + 0] + bias[col];
                    float v1 = acc[ms][ns][half * 2 + 1] + bias[col + 1];
                    *(float2*)(outf + (size_t)row * ldof + col) = make_float2(v0, v1);
                }
            } else {
                float* op = outf + (size_t)row * ldof + colbase + qc * 2;
                float mx = -1e30f;
#pragma unroll
                for (int ns = 0; ns < 8; ++ns) {
                    float v0 = acc[ms][ns][half * 2 + 0];
                    float v1 = acc[ms][ns][half * 2 + 1];
                    *(float2*)(op + ns * 8) = make_float2(v0, v1);
                    mx = fmaxf(mx, fmaxf(v0, v1));
                }
                mx = fmaxf(mx, __shfl_xor_sync(0xffffffffu, mx, 1));
                mx = fmaxf(mx, __shfl_xor_sync(0xffffffffu, mx, 2));
                float sm = 0.f;
#pragma unroll
                for (int ns = 0; ns < 8; ++ns) {
                    sm += __expf(acc[ms][ns][half * 2 + 0] - mx);
                    sm += __expf(acc[ms][ns][half * 2 + 1] - mx);
                }
                sm += __shfl_xor_sync(0xffffffffu, sm, 1);
                sm += __shfl_xor_sync(0xffffffffu, sm, 2);
                if (qc == 0)
                    part[(size_t)row * NT2_ + blockIdx.x * 2 + nj] = make_float2(mx, sm);
            }
        }
    }
}

// ---------------- K6: combine partials -> lse ----------------
__global__ void lse_kernel() {
    int row = blockIdx.x, lane = threadIdx.x;
    float m = -1e30f, s = 0.f;
    for (int i = lane; i < NT2_; i += 32) {
        float2 p = g_part[(size_t)row * NT2_ + i];
        if (p.x > m) { s = s * __expf(m - p.x) + p.y; m = p.x; }
        else         { s = s + p.y * __expf(p.x - m); }
    }
#pragma unroll
    for (int o = 16; o > 0; o >>= 1) {
        float mo = __shfl_xor_sync(0xffffffffu, m, o);
        float so = __shfl_xor_sync(0xffffffffu, s, o);
        if (mo > m) { s = s * __expf(m - mo) + so; m = mo; }
        else        { s = s + so * __expf(mo - m); }
    }
    if (lane == 0) g_lse[row] = m + logf(s);
}

// ---------------- K7: out -= lse[row] ----------------
__global__ void sub_kernel(float* __restrict__ out) {
    size_t idx = (size_t)blockIdx.x * 256 + threadIdx.x;
    int row = (int)(idx / (V_ / 4));
    float4 v = ((float4*)out)[idx];
    float l = g_lse[row];
    v.x -= l; v.y -= l; v.z -= l; v.w -= l;
    ((float4*)out)[idx] = v;
}

// ---------------- launch ----------------
extern "C" void kernel_launch(void* const* d_in, const int* in_sizes, int n_in,
                              void* d_out, int out_size) {
    const int*   x     = (const int*)d_in[0];
    const float* emb_W = (const float*)d_in[1];
    const float* W_ih  = (const float*)d_in[2];
    const float* W_hh  = (const float*)d_in[3];
    const float* b_ih  = (const float*)d_in[4];
    const float* b_hh  = (const float*)d_in[5];
    const float* lin_W = (const float*)d_in[6];
    const float* lin_b = (const float*)d_in[7];
    float* out = (float*)d_out;

    float* gx;
    __nv_bfloat16 *featbf, *embh, *linbf, *wihbf, *logbf;
    float2* part;
    cudaGetSymbolAddress((void**)&featbf, g_featbf);
    cudaGetSymbolAddress((void**)&gx,     g_gx);
    cudaGetSymbolAddress((void**)&embh,   g_embh);
    cudaGetSymbolAddress((void**)&linbf,  g_linbf);
    cudaGetSymbolAddress((void**)&wihbf,  g_wihbf);
    cudaGetSymbolAddress((void**)&logbf,  g_logbf);
    cudaGetSymbolAddress((void**)&part,   g_part);

    cudaFuncSetAttribute(hmma_kernel<0>, cudaFuncAttributeMaxDynamicSharedMemorySize, HSMEM);
    cudaFuncSetAttribute(hmma_kernel<1>, cudaFuncAttributeMaxDynamicSharedMemorySize, HSMEM);
    cudaFuncSetAttribute(hmma_kernel<2>, cudaFuncAttributeMaxDynamicSharedMemorySize, HSMEM);

    // 1: fused prep (pack W_hh fragments + embed + cvt tables)
    prep_kernel<<<PREP_BLOCKS, 256>>>(W_hh, x, emb_W, lin_W, W_ih);
    // 2: gx = emb_bf16 @ W_ih_bf16^T + b_ih  (HMMA, fp32 out)
    hmma_kernel<2><<<dim3(G_ / 128, T_ / 128), 256, HSMEM>>>(featbf + H_, F_, wihbf, E_, E_,
                                                             b_ih, nullptr, 0, gx, G_, nullptr);
    // 3: GRU recurrence (HMMA GEMV, sharded barrier)
    gru_kernel<<<GRU_CTAS, 256>>>(x, b_hh);
    // 4: logits = tanh(featbf @ linbf^T + lin_b) -> bf16   [profiled]
    hmma_kernel<0><<<dim3(E_ / 128, T_ / 128), 256, HSMEM>>>(featbf, F_, linbf, F_, F_,
                                                             lin_b, logbf, E_, nullptr, 0, nullptr);
    // 5: scores + fused softmax partials
    hmma_kernel<1><<<dim3(NT_, T_ / 128), 256, HSMEM>>>(logbf, E_, embh, E_, E_,
                                                        nullptr, nullptr, 0, out, V_, part);
    // 6, 7
    lse_kernel<<<T_, 32>>>();
    sub_kernel<<<(T_ * (V_ / 4)) / 256, 256>>>(out);
}